// round 2
// baseline (speedup 1.0000x reference)
#include <cuda_runtime.h>
#include <cuda_bf16.h>

// Problem constants (fixed by the dataset)
#define NN 100000
#define EE 1600000
#define DD 128

// Scratch (allocation-free rule: __device__ globals)
__device__ float d_g[(size_t)NN * DD];     // g = dinv[i] * (x @ Wc^T)   (51.2 MB)
__device__ float d_dinv[NN];
__device__ int   d_deg[NN];
__device__ float d_Wc[DD * DD];            // Wc = W_gcn @ W_lin

// ---------------------------------------------------------------------------
// 1) deg init (self loop => 1)
__global__ void init_deg_kernel(int n) {
    int i = blockIdx.x * blockDim.x + threadIdx.x;
    if (i < n) d_deg[i] = 1;
}

// 2) zero d_out (poisoned by harness)
__global__ void zero_out_kernel(float4* __restrict__ out4, int n4) {
    int i = blockIdx.x * blockDim.x + threadIdx.x;
    if (i < n4) out4[i] = make_float4(0.f, 0.f, 0.f, 0.f);
}

// 3) count in-degrees over edge targets (edge_index is int32 on device)
__global__ void count_deg_kernel(const int* __restrict__ ei, int E) {
    int e = blockIdx.x * blockDim.x + threadIdx.x;
    if (e < E) {
        int c = __ldg(&ei[E + e]);
        atomicAdd(&d_deg[c], 1);
    }
}

// 4) dinv = rsqrt(deg)
__global__ void dinv_kernel(int n) {
    int i = blockIdx.x * blockDim.x + threadIdx.x;
    if (i < n) d_dinv[i] = rsqrtf((float)d_deg[i]);
}

// 5) Wc[i][j] = sum_k Wg[i][k] * Wl[k][j]   (h = x @ Wc^T)
__global__ void combine_w_kernel(const float* __restrict__ Wl,
                                 const float* __restrict__ Wg) {
    int i = blockIdx.x;   // 128 blocks
    int j = threadIdx.x;  // 128 threads
    float s0 = 0.f, s1 = 0.f, s2 = 0.f, s3 = 0.f;
#pragma unroll 8
    for (int k = 0; k < DD; k += 4) {
        s0 += __ldg(&Wg[i * DD + k + 0]) * __ldg(&Wl[(k + 0) * DD + j]);
        s1 += __ldg(&Wg[i * DD + k + 1]) * __ldg(&Wl[(k + 1) * DD + j]);
        s2 += __ldg(&Wg[i * DD + k + 2]) * __ldg(&Wl[(k + 2) * DD + j]);
        s3 += __ldg(&Wg[i * DD + k + 3]) * __ldg(&Wl[(k + 3) * DD + j]);
    }
    d_Wc[i * DD + j] = (s0 + s1) + (s2 + s3);
}

// 6) g[i][:] = dinv[i] * (x[i] @ Wc^T)
//    Block: 64 rows x 128 cols, K in chunks of 32. 256 threads.
__global__ __launch_bounds__(256, 2) void gemm_g_kernel(const float* __restrict__ x, int n) {
    __shared__ float xs[64][32];   // row-major x chunk (reads are warp-broadcast)
    __shared__ float ws[32][128];  // ws[k][c]; float4 reads along c => conflict-free

    const int tid = threadIdx.x;
    const int row0 = blockIdx.x * 64;
    const int tx = tid & 31;
    const int ty = tid >> 5;

    float4 acc[8];
#pragma unroll
    for (int i = 0; i < 8; i++) acc[i] = make_float4(0.f, 0.f, 0.f, 0.f);

    const float4* x4 = (const float4*)x;
    const float4* w4 = (const float4*)d_Wc;

    for (int kb = 0; kb < 4; kb++) {
        // load x tile: 64 rows x 8 float4
#pragma unroll
        for (int rr = 0; rr < 2; rr++) {
            int r = (tid >> 3) + rr * 32;
            int f = tid & 7;                       // float4 index within chunk
            int grow = row0 + r;
            float4 v = make_float4(0.f, 0.f, 0.f, 0.f);
            if (grow < n) v = __ldg(&x4[(long long)grow * 32 + kb * 8 + f]);
            *(float4*)&xs[r][f * 4] = v;
        }
        // load W chunk transposed: ws[k][c]
        {
            int c = tid >> 1;
            int hb = (tid & 1) * 4;
#pragma unroll
            for (int m = 0; m < 4; m++) {
                float4 v = __ldg(&w4[c * 32 + kb * 8 + hb + m]);
                int kl = (hb + m) * 4;
                ws[kl + 0][c] = v.x;
                ws[kl + 1][c] = v.y;
                ws[kl + 2][c] = v.z;
                ws[kl + 3][c] = v.w;
            }
        }
        __syncthreads();

#pragma unroll 8
        for (int k = 0; k < 32; k++) {
            float4 w = *(const float4*)&ws[k][tx * 4];
#pragma unroll
            for (int i = 0; i < 8; i++) {
                float xv = xs[ty * 8 + i][k];
                acc[i].x += xv * w.x;
                acc[i].y += xv * w.y;
                acc[i].z += xv * w.z;
                acc[i].w += xv * w.w;
            }
        }
        __syncthreads();
    }

    float4* g4 = (float4*)d_g;
#pragma unroll
    for (int i = 0; i < 8; i++) {
        int r = row0 + ty * 8 + i;
        if (r < n) {
            float di = d_dinv[r];
            float4 o;
            o.x = acc[i].x * di;
            o.y = acc[i].y * di;
            o.z = acc[i].z * di;
            o.w = acc[i].w * di;
            g4[(long long)r * 32 + tx] = o;
        }
    }
}

// 7) scatter: one warp per edge (x EPW), vectorized float4 reductions into out
#define EPW 4
__global__ void scatter_kernel(const int* __restrict__ ei,
                               float* __restrict__ out, int E) {
    int warp = (blockIdx.x * blockDim.x + threadIdx.x) >> 5;
    int lane = threadIdx.x & 31;
    const float4* g4 = (const float4*)d_g;
    long long base = (long long)warp * EPW;
#pragma unroll
    for (int t = 0; t < EPW; t++) {
        long long e = base + t;
        if (e >= E) return;
        int r = __ldg(&ei[e]);
        int c = __ldg(&ei[E + e]);
        float4 v = __ldg(&g4[(long long)r * 32 + lane]);
        float* addr = out + (long long)c * DD + lane * 4;
        asm volatile("red.global.add.v4.f32 [%0], {%1,%2,%3,%4};"
                     :: "l"(addr), "f"(v.x), "f"(v.y), "f"(v.z), "f"(v.w)
                     : "memory");
    }
}

// 8) finalize: out[i][:] = dinv[i] * (acc + g[i]) + b
__global__ void finalize_kernel(const float* __restrict__ b,
                                float* __restrict__ out, int n4total) {
    int idx = blockIdx.x * blockDim.x + threadIdx.x;
    if (idx >= n4total) return;
    int i = idx >> 5;      // node
    int q = idx & 31;      // float4 within row
    float di = d_dinv[i];
    float4 a = ((float4*)out)[idx];
    float4 g = ((const float4*)d_g)[idx];
    float4 bb = __ldg(&((const float4*)b)[q]);
    float4 o;
    o.x = di * (a.x + g.x) + bb.x;
    o.y = di * (a.y + g.y) + bb.y;
    o.z = di * (a.z + g.z) + bb.z;
    o.w = di * (a.w + g.w) + bb.w;
    ((float4*)out)[idx] = o;
}

extern "C" void kernel_launch(void* const* d_in, const int* in_sizes, int n_in,
                              void* d_out, int out_size) {
    const float* x  = (const float*)d_in[0];
    const int*   ei = (const int*)d_in[1];     // int32 (JAX x64 disabled)
    const float* Wl = (const float*)d_in[2];
    const float* Wg = (const float*)d_in[3];
    const float* b  = (const float*)d_in[4];
    float* out = (float*)d_out;

    int n = in_sizes[0] / DD;     // 100000
    int E = in_sizes[1] / 2;      // 1600000
    int n4 = n * (DD / 4);        // float4 count of out/g

    init_deg_kernel<<<(n + 255) / 256, 256>>>(n);
    zero_out_kernel<<<(n4 + 255) / 256, 256>>>((float4*)out, n4);
    count_deg_kernel<<<(E + 255) / 256, 256>>>(ei, E);
    dinv_kernel<<<(n + 255) / 256, 256>>>(n);
    combine_w_kernel<<<DD, DD>>>(Wl, Wg);
    gemm_g_kernel<<<(n + 63) / 64, 256>>>(x, n);

    int warps = (E + EPW - 1) / EPW;
    int sblocks = (warps * 32 + 255) / 256;
    scatter_kernel<<<sblocks, 256>>>(ei, out, E);

    finalize_kernel<<<(n4 + 255) / 256, 256>>>(b, out, n4);
}